// round 13
// baseline (speedup 1.0000x reference)
#include <cuda_runtime.h>
#include <cstdint>
#include <cstddef>

#define FULLMASK 0xFFFFFFFFu

// ---------------- problem constants ------------------------------------------
constexpr int B  = 32;
constexpr int H  = 768;
constexpr int KQ = 131072;

// ---------------- mma.sync matmul tiling --------------------------------------
constexpr int MROWS = 128;
constexpr int NCHT  = H / 64;
constexpr int TCTHREADS = 128;
constexpr int AST   = 36;
constexpr int SM_A     = 0;
constexpr int SM_B     = 36864;
constexpr int SM_CLB   = 46080;
constexpr int SM_LBB   = 46208;
constexpr int SMEM_TC  = 46336;
constexpr int SM_SIMS  = 0;
constexpr int SM_STAGE = 16896;
constexpr int SM_WC    = 33280;
constexpr int SM_LOFS  = 34304;
constexpr int SM_BASE  = 34560;
constexpr int SM_CNT   = 34816;

// ---------------- scratch ----------------------------------------------------
__device__ unsigned int g_bufP [(size_t)B * KQ];
__device__ unsigned int g_bufN0[(size_t)B * KQ];
__device__ unsigned int g_bufN1[(size_t)B * KQ];
__device__ unsigned int g_histA[B * 8192];
__device__ int g_cntP[B];
__device__ int g_cntN[B];
__device__ int g_pmm[2];
__device__ unsigned int g_posPart[B * 20];    // 2 chunks x 10 per row
__device__ unsigned int g_qhi[B * H / 2];
__device__ unsigned int g_qlo[B * H / 2];

__device__ __forceinline__ unsigned int keyOf(float f) {
    unsigned int u = __float_as_uint(f);
    return (u & 0x80000000u) ? u : (~u & 0x7FFFFFFFu);
}
__device__ __forceinline__ float valOf(unsigned int d) {
    unsigned int u = (d & 0x80000000u) ? d : (~d & 0x7FFFFFFFu);
    return __uint_as_float(u);
}
__device__ __forceinline__ uint32_t smem_to_u32(const void* p) {
    uint32_t a;
    asm("{ .reg .u64 t; cvta.to.shared.u64 t, %1; cvt.u32.u64 %0, t; }" : "=r"(a) : "l"(p));
    return a;
}

#define CVT_BF16X2(res, e0, e1) \
    asm("cvt.rn.satfinite.bf16x2.f32 %0, %1, %2;" : "=r"(res) : "f"(e1), "f"(e0))

__device__ __forceinline__ void mma_bf16(float* d, const unsigned* a, const unsigned* b) {
    asm volatile("mma.sync.aligned.m16n8k16.row.col.f32.bf16.bf16.f32 "
                 "{%0,%1,%2,%3}, {%4,%5,%6,%7}, {%8,%9}, {%0,%1,%2,%3};"
                 : "+f"(d[0]), "+f"(d[1]), "+f"(d[2]), "+f"(d[3])
                 : "r"(a[0]), "r"(a[1]), "r"(a[2]), "r"(a[3]),
                   "r"(b[0]), "r"(b[1]));
}
__device__ __forceinline__ void ldsm_x4(unsigned* r, uint32_t addr) {
    asm volatile("ldmatrix.sync.aligned.m8n8.x4.shared.b16 {%0,%1,%2,%3}, [%4];"
                 : "=r"(r[0]), "=r"(r[1]), "=r"(r[2]), "=r"(r[3]) : "r"(addr));
}

// ---------------- kernel: zero counters + split queries into bf16 hi/lo --------
__global__ void prep_q(const float* __restrict__ q) {
    int w = blockIdx.x * 256 + threadIdx.x;
    if (w < B) { g_cntP[w] = 0; g_cntN[w] = 0; }
    if (w >= B * H / 2) return;
    float x0 = q[2 * w], x1 = q[2 * w + 1];
    unsigned int whi; CVT_BF16X2(whi, x0, x1);
    float h0 = __uint_as_float(whi << 16);
    float h1 = __uint_as_float(whi & 0xFFFF0000u);
    unsigned int wlo; CVT_BF16X2(wlo, x0 - h0, x1 - h1);
    g_qhi[w] = whi;
    g_qlo[w] = wlo;
}

// ---------------- kernel 1: mma.sync + ldmatrix matmul + mask partition --------
__global__ __launch_bounds__(TCTHREADS, 2)
void mm_tc(const float* __restrict__ fq,
           const int* __restrict__ lab_q, const int* __restrict__ clu_q,
           const int* __restrict__ lab_k, const int* __restrict__ clu_k)
{
    extern __shared__ char sm[];
    const uint32_t smb = smem_to_u32(sm);
    const int t = threadIdx.x;
    const int w = t >> 5, lane = t & 31;
    const int g = lane >> 2, c4 = lane & 3;
    const int k0 = blockIdx.x * MROWS;

    int* s_clb = (int*)(sm + SM_CLB);
    int* s_lbb = (int*)(sm + SM_LBB);
    if (t < 32) { s_clb[t] = clu_q[t]; s_lbb[t] = lab_q[t]; }

    unsigned int* smAh = (unsigned int*)(sm + SM_A);
    unsigned int* smAl = smAh + MROWS * AST;
    unsigned int* smBh = (unsigned int*)(sm + SM_B);
    unsigned int* smBl = smBh + 32 * AST;

    uint32_t aAddr[2][2];
    {
        int row = w * 32 + (lane & 7) + ((lane >> 3) & 1) * 8;
        int word = ((lane >> 4) & 1) * 4;
        #pragma unroll
        for (int mt = 0; mt < 2; mt++) {
            uint32_t off = (uint32_t)(((row + mt * 16) * AST + word) * 4);
            aAddr[0][mt] = smb + SM_A + off;
            aAddr[1][mt] = smb + SM_A + 18432u + off;
        }
    }
    uint32_t bAddr[2][2];
    {
        int row = (lane & 7) + ((lane >> 4) & 1) * 8;
        int word = ((lane >> 3) & 1) * 4;
        #pragma unroll
        for (int ntp = 0; ntp < 2; ntp++) {
            uint32_t off = (uint32_t)(((row + ntp * 16) * AST + word) * 4);
            bAddr[0][ntp] = smb + SM_B + off;
            bAddr[1][ntp] = smb + SM_B + 4608u + off;
        }
    }

    const float4* gA = (const float4*)(fq + (size_t)(k0 + t) * H);

    float4 areg[16];
    unsigned int bhr[8], blr[8];

    auto loadChunk = [&](int c) {
        const float4* p = gA + c * 16;
        #pragma unroll
        for (int ii = 0; ii < 16; ii++) areg[ii] = p[ii];
        #pragma unroll
        for (int ps = 0; ps < 8; ps++) {
            int idx = ps * TCTHREADS + t;
            int n = idx >> 5, wd = idx & 31;
            bhr[ps] = g_qhi[n * (H / 2) + c * 32 + wd];
            blr[ps] = g_qlo[n * (H / 2) + c * 32 + wd];
        }
    };
    auto storeChunk = [&]() {
        #pragma unroll
        for (int ii = 0; ii < 16; ii += 2) {
            float4 v0 = areg[ii], v1 = areg[ii + 1];
            unsigned int h0, h1, h2, h3, l0, l1, l2, l3;
            CVT_BF16X2(h0, v0.x, v0.y);
            CVT_BF16X2(h1, v0.z, v0.w);
            CVT_BF16X2(h2, v1.x, v1.y);
            CVT_BF16X2(h3, v1.z, v1.w);
            float r0 = v0.x - __uint_as_float(h0 << 16);
            float r1 = v0.y - __uint_as_float(h0 & 0xFFFF0000u);
            float r2 = v0.z - __uint_as_float(h1 << 16);
            float r3 = v0.w - __uint_as_float(h1 & 0xFFFF0000u);
            float r4 = v1.x - __uint_as_float(h2 << 16);
            float r5 = v1.y - __uint_as_float(h2 & 0xFFFF0000u);
            float r6 = v1.z - __uint_as_float(h3 << 16);
            float r7 = v1.w - __uint_as_float(h3 & 0xFFFF0000u);
            CVT_BF16X2(l0, r0, r1);
            CVT_BF16X2(l1, r2, r3);
            CVT_BF16X2(l2, r4, r5);
            CVT_BF16X2(l3, r6, r7);
            *(uint4*)&smAh[t * AST + 2 * ii] = make_uint4(h0, h1, h2, h3);
            *(uint4*)&smAl[t * AST + 2 * ii] = make_uint4(l0, l1, l2, l3);
        }
        #pragma unroll
        for (int ps = 0; ps < 8; ps++) {
            int idx = ps * TCTHREADS + t;
            int n = idx >> 5, wd = idx & 31;
            smBh[n * AST + wd] = bhr[ps];
            smBl[n * AST + wd] = blr[ps];
        }
    };

    float acc[2][4][4];
    #pragma unroll
    for (int mt = 0; mt < 2; mt++)
        #pragma unroll
        for (int nt = 0; nt < 4; nt++)
            #pragma unroll
            for (int r = 0; r < 4; r++) acc[mt][nt][r] = 0.0f;

    loadChunk(0);
    for (int c = 0; c < NCHT; c++) {
        if (c > 0) __syncthreads();
        storeChunk();
        if (c + 1 < NCHT) loadChunk(c + 1);
        __syncthreads();

        #pragma unroll
        for (int ks = 0; ks < 4; ks++) {
            const uint32_t kb = (uint32_t)(ks * 32);
            unsigned int ah[2][4], al[2][4], bh[4][2], bl[4][2];
            #pragma unroll
            for (int mt = 0; mt < 2; mt++) {
                ldsm_x4(ah[mt], aAddr[0][mt] + kb);
                ldsm_x4(al[mt], aAddr[1][mt] + kb);
            }
            #pragma unroll
            for (int ntp = 0; ntp < 2; ntp++) {
                unsigned int rh[4], rl[4];
                ldsm_x4(rh, bAddr[0][ntp] + kb);
                ldsm_x4(rl, bAddr[1][ntp] + kb);
                bh[2 * ntp][0] = rh[0]; bh[2 * ntp][1] = rh[1];
                bh[2 * ntp + 1][0] = rh[2]; bh[2 * ntp + 1][1] = rh[3];
                bl[2 * ntp][0] = rl[0]; bl[2 * ntp][1] = rl[1];
                bl[2 * ntp + 1][0] = rl[2]; bl[2 * ntp + 1][1] = rl[3];
            }
            #pragma unroll
            for (int mt = 0; mt < 2; mt++)
                #pragma unroll
                for (int nt = 0; nt < 4; nt++)
                    mma_bf16(acc[mt][nt], ah[mt], bh[nt]);
            #pragma unroll
            for (int mt = 0; mt < 2; mt++)
                #pragma unroll
                for (int nt = 0; nt < 4; nt++)
                    mma_bf16(acc[mt][nt], ah[mt], bl[nt]);
            #pragma unroll
            for (int mt = 0; mt < 2; mt++)
                #pragma unroll
                for (int nt = 0; nt < 4; nt++)
                    mma_bf16(acc[mt][nt], al[mt], bh[nt]);
        }
    }
    __syncthreads();

    float* sims = (float*)(sm + SM_SIMS);
    #pragma unroll
    for (int mt = 0; mt < 2; mt++) {
        int r0 = w * 32 + mt * 16 + g;
        #pragma unroll
        for (int nt = 0; nt < 4; nt++) {
            int cb = nt * 8 + 2 * c4;
            sims[r0 * 33 + cb]           = acc[mt][nt][0];
            sims[r0 * 33 + cb + 1]       = acc[mt][nt][1];
            sims[(r0 + 8) * 33 + cb]     = acc[mt][nt][2];
            sims[(r0 + 8) * 33 + cb + 1] = acc[mt][nt][3];
        }
    }
    __syncthreads();

    unsigned int* stage = (unsigned int*)(sm + SM_STAGE);
    int* s_wc   = (int*)(sm + SM_WC);
    int* s_lofs = (int*)(sm + SM_LOFS);
    int* s_base = (int*)(sm + SM_BASE);
    int* s_cnt  = (int*)(sm + SM_CNT);

    int clk = clu_k[k0 + t];
    int lbk = lab_k[k0 + t];
    float myS[32];
    #pragma unroll
    for (int b = 0; b < 32; b++) myS[b] = sims[t * 33 + b];

    #pragma unroll
    for (int b = 0; b < 32; b++) {
        int neg = (clk == s_clb[b]) != (lbk == s_lbb[b]);
        unsigned int mask = __ballot_sync(FULLMASK, neg);
        if (lane == 0) {
            int cn = __popc(mask);
            s_wc[(b * 2 + 1) * 4 + w] = cn;
            s_wc[(b * 2) * 4 + w] = 32 - cn;
        }
    }
    __syncthreads();
    if (t < 64) {
        int run = 0, st[4];
        #pragma unroll
        for (int ww = 0; ww < 4; ww++) { st[ww] = run; run += s_wc[t * 4 + ww]; }
        #pragma unroll
        for (int ww = 0; ww < 4; ww++) s_wc[t * 4 + ww] = st[ww];
        s_cnt[t] = run;
        int b = t >> 1, neg = t & 1;
        s_base[t] = run ? atomicAdd(neg ? &g_cntN[b] : &g_cntP[b], run) : 0;
    }
    __syncthreads();
    if (t == 0) {
        int run = 0;
        for (int s = 0; s < 64; s++) { s_lofs[s] = run; run += s_cnt[s]; }
    }
    __syncthreads();
    {
        unsigned int below = (1u << lane) - 1u;
        #pragma unroll
        for (int b = 0; b < 32; b++) {
            int neg = (clk == s_clb[b]) != (lbk == s_lbb[b]);
            unsigned int mask = __ballot_sync(FULLMASK, neg);
            int seg = b * 2 + neg;
            int rank = neg ? __popc(mask & below) : __popc(~mask & below);
            stage[s_lofs[seg] + s_wc[seg * 4 + w] + rank] = keyOf(myS[b]);
        }
    }
    __syncthreads();
    for (int s = w * 16; s < w * 16 + 16; s++) {
        int cnt = s_cnt[s];
        int b = s >> 1, neg = s & 1;
        unsigned int* dst = (neg ? g_bufN0 : g_bufP) + (size_t)b * KQ + s_base[s];
        const unsigned int* srcP = stage + s_lofs[s];
        for (int i = lane; i < cnt; i += 32) dst[i] = srcP[i];
    }
}

// ---------------- per-pass histogram (+ fused minmax on pass 0) ----------------
__global__ void rs_hist(int shift, int srcSel, int doMinmax,
                        const int* __restrict__ topk) {
    int chunk = blockIdx.x, row = blockIdx.y;
    int t = threadIdx.x;
    if (doMinmax && chunk == 0 && row == 0 && t < 32) {
        int cp = g_cntP[t], cn = g_cntN[t];
        #pragma unroll
        for (int off = 16; off; off >>= 1) {
            cp = min(cp, __shfl_down_sync(FULLMASK, cp, off));
            cn = min(cn, __shfl_down_sync(FULLMASK, cn, off));
        }
        if (t == 0) { g_pmm[0] = min(cp, topk[0]); g_pmm[1] = cn; }
    }
    int n = g_cntN[row];
    int s0 = chunk * 4096;
    __shared__ int h[256];
    h[t] = 0;
    __syncthreads();
    if (s0 < n) {
        const unsigned int* in = (srcSel ? g_bufN1 : g_bufN0) + (size_t)row * KQ;
        int lim = min(4096, n - s0);
        for (int i = t; i < lim; i += 256)
            atomicAdd(&h[(in[s0 + i] >> shift) & 255], 1);
    }
    __syncthreads();
    g_histA[row * 8192 + t * 32 + chunk] = h[t];
}

// ---------------- scan ---------------------------------------------------------
__global__ void rs_scan() {
    int row = blockIdx.x;
    unsigned int* a = g_histA + row * 8192;
    int t = threadIdx.x;
    int v[32]; int sum = 0;
    int base = t * 32;
    #pragma unroll
    for (int i = 0; i < 32; i++) { v[i] = (int)a[base + i]; sum += v[i]; }
    __shared__ int ps[256];
    ps[t] = sum;
    __syncthreads();
    for (int off = 1; off < 256; off <<= 1) {
        int x = (t >= off) ? ps[t - off] : 0;
        __syncthreads();
        ps[t] += x;
        __syncthreads();
    }
    int run = (t > 0) ? ps[t - 1] : 0;
    #pragma unroll
    for (int i = 0; i < 32; i++) { int tmp = v[i]; a[base + i] = (unsigned)run; run += tmp; }
}

// ---------------- top-10 of positives (2 blocks/row, 128 keys/thread) ----------
__device__ __forceinline__ void insert10(unsigned int (&best)[10], unsigned int k) {
    if (k < best[9]) {
        int j = 9;
        #pragma unroll
        for (int s = 0; s < 9; s++) {
            if (j > 0 && best[j - 1] > k) { best[j] = best[j - 1]; j--; }
        }
        best[j] = k;
    }
}

__global__ void pos_part() {
    int c = blockIdx.x, row = blockIdx.y;   // c in {0,1}
    int n = g_cntP[row];
    int per = (n + 1) >> 1;
    int s = c * per, e = min(s + per, n);
    const unsigned int* src = g_bufP + (size_t)row * KQ;
    int t = threadIdx.x;
    int w = t >> 5, lane = t & 31;
    unsigned int best[10];
    #pragma unroll
    for (int i = 0; i < 10; i++) best[i] = 0xFFFFFFFFu;
    for (int base = s; base < e; base += 2048) {
        unsigned int k[8];
        #pragma unroll
        for (int qn = 0; qn < 8; qn++) {
            int idx = base + qn * 256 + t;
            k[qn] = (idx < e) ? src[idx] : 0xFFFFFFFFu;
        }
        #pragma unroll
        for (int qn = 0; qn < 8; qn++) insert10(best, k[qn]);
    }
    __shared__ unsigned int sh[8 * 10];
    #pragma unroll
    for (int r = 0; r < 10; r++) {
        unsigned int cand = best[0];
        unsigned int wmin = cand;
        #pragma unroll
        for (int off = 16; off; off >>= 1)
            wmin = min(wmin, __shfl_xor_sync(FULLMASK, wmin, off));
        unsigned int bal = __ballot_sync(FULLMASK, cand == wmin);
        int leader = __ffs(bal) - 1;
        if (lane == leader) {
            #pragma unroll
            for (int i = 0; i < 9; i++) best[i] = best[i + 1];
            best[9] = 0xFFFFFFFFu;
        }
        if (lane == 0) sh[w * 10 + r] = wmin;
    }
    __syncthreads();
    if (w == 0) {
        int head = 0;
        for (int r = 0; r < 10; r++) {
            unsigned int cand = (lane < 8) ? sh[lane * 10 + head] : 0xFFFFFFFFu;
            unsigned int wmin = cand;
            #pragma unroll
            for (int off = 16; off; off >>= 1)
                wmin = min(wmin, __shfl_xor_sync(FULLMASK, wmin, off));
            unsigned int bal = __ballot_sync(FULLMASK, cand == wmin && lane < 8);
            int leader = __ffs(bal) - 1;
            if (lane == leader) head++;
            if (lane == 0) g_posPart[row * 20 + c * 10 + r] = wmin;
        }
    }
}

// ---------------- radix scatter (3 passes) -------------------------------------
__global__ __launch_bounds__(256)
void rs_scatter(int shift, int srcSel) {
    int chunk = blockIdx.x, row = blockIdx.y;
    int n = g_cntN[row];
    int s0 = chunk * 4096;
    if (s0 >= n) return;
    const unsigned int* in  = (srcSel ? g_bufN1 : g_bufN0) + (size_t)row * KQ;
    unsigned int*       out = (srcSel ? g_bufN0 : g_bufN1) + (size_t)row * KQ;
    const unsigned int* Hb  = g_histA + row * 8192;

    __shared__ unsigned int sKeys[4096];
    __shared__ int wh[8 * 256];
    __shared__ int gb[256];
    __shared__ int lofs[256];
    __shared__ int ps[256];

    int t = threadIdx.x;
    int w = t >> 5, lane = t & 31;
    int wbase = s0 + 512 * w;

    unsigned int myKeys[16];
    #pragma unroll
    for (int j = 0; j < 16; j++) {
        int idx = wbase + 32 * j + lane;
        myKeys[j] = (idx < n) ? in[idx] : 0xFFFFFFFFu;
    }

    #pragma unroll
    for (int qq = 0; qq < 8; qq++) wh[qq * 256 + t] = 0;
    __syncthreads();

    #pragma unroll
    for (int j = 0; j < 16; j++) {
        int idx = wbase + 32 * j + lane;
        if (idx < n) atomicAdd(&wh[w * 256 + ((myKeys[j] >> shift) & 255)], 1);
    }
    __syncthreads();

    int tot = 0; int wstart[8];
    #pragma unroll
    for (int ww = 0; ww < 8; ww++) { wstart[ww] = tot; tot += wh[ww * 256 + t]; }
    ps[t] = tot;
    gb[t] = (int)Hb[t * 32 + chunk];
    __syncthreads();
    for (int off = 1; off < 256; off <<= 1) {
        int x = (t >= off) ? ps[t - off] : 0;
        __syncthreads();
        ps[t] += x;
        __syncthreads();
    }
    int lo = ps[t] - tot;
    lofs[t] = lo;
    #pragma unroll
    for (int ww = 0; ww < 8; ww++) wh[ww * 256 + t] = lo + wstart[ww];
    __syncthreads();

    #pragma unroll
    for (int j = 0; j < 16; j++) {
        int idx = wbase + 32 * j + lane;
        bool val = idx < n;
        unsigned int key = myKeys[j];
        int d = (key >> shift) & 255;
        unsigned int vm = __ballot_sync(FULLMASK, val);
        unsigned int peers = FULLMASK;
        #pragma unroll
        for (int bb = 0; bb < 8; ++bb) {
            unsigned int vote = __ballot_sync(FULLMASK, (d >> bb) & 1);
            peers &= ((d >> bb) & 1) ? vote : ~vote;
        }
        peers &= vm;
        int rank = __popc(peers & ((1u << lane) - 1u));
        int leader = peers ? (__ffs(peers) - 1) : 0;
        int basePos = 0;
        if (val && rank == 0) basePos = atomicAdd(&wh[w * 256 + d], __popc(peers));
        basePos = __shfl_sync(FULLMASK, basePos, leader);
        if (val) sKeys[basePos + rank] = key;
    }
    __syncthreads();

    int lim = min(4096, n - s0);
    for (int pos = t; pos < lim; pos += 256) {
        unsigned int key = sKeys[pos];
        int d = (key >> shift) & 255;
        out[gb[d] + (pos - lofs[d])] = key;
    }
}

// ---------------- writer (final sorted negatives in g_bufN1) -------------------
// c==0 threads do the pos merge inline: p-th smallest of the 2x10 partial lists.
__global__ void write_k(float* __restrict__ out) {
    int r = blockIdx.y;
    unsigned int pm = (unsigned int)g_pmm[0];
    unsigned int nm = (unsigned int)g_pmm[1];
    if ((unsigned)r >= 32u * pm) return;
    unsigned int width = nm + 1u;
    unsigned int b = (unsigned)r / pm;
    unsigned int p = (unsigned)r - b * pm;
    const float invT = 1.0f / 0.07f;
    size_t rowBase = (size_t)r * width;
    const unsigned int* negRow = g_bufN1 + (size_t)b * KQ;

    unsigned int qlen = (width + 3u) >> 2;
    unsigned int c = blockIdx.x * qlen + threadIdx.x;
    unsigned int cend = min((blockIdx.x + 1u) * qlen, width);
    if (c >= cend) return;
    if (c == 0u) {
        const unsigned int* parts = g_posPart + b * 20;
        unsigned int res = 0u;
        #pragma unroll 4
        for (int j = 0; j < 20; j++) {
            unsigned int xj = parts[j];
            int rank = 0;
            for (int i = 0; i < 20; i++) {
                unsigned int xi = parts[i];
                rank += (xi < xj) || (xi == xj && i < j);
            }
            if (rank == (int)p) res = xj;
        }
        out[rowBase] = valOf(res) * invT;
        c += 256u;
        if (c >= cend) return;
    }
    unsigned int num = p * nm + (c - 1u);
    unsigned int qi = num / pm;
    unsigned int rem = num - qi * pm;
    unsigned int d256 = 256u / pm;
    unsigned int r256 = 256u - d256 * pm;
    while (c < cend) {
        out[rowBase + c] = valOf(negRow[qi]) * invT;
        c += 256u;
        qi += d256;
        rem += r256;
        if (rem >= pm) { rem -= pm; qi += 1u; }
    }
}

// ---------------- launcher ----------------------------------------------------
extern "C" void kernel_launch(void* const* d_in, const int* in_sizes, int n_in,
                              void* d_out, int out_size) {
    const float* q     = (const float*)d_in[0];
    const float* fq    = (const float*)d_in[1];
    const int* lab_q   = (const int*)d_in[2];
    const int* clu_q   = (const int*)d_in[3];
    const int* lab_k   = (const int*)d_in[4];
    const int* clu_k   = (const int*)d_in[5];
    const int* topk    = (const int*)d_in[6];
    float* out = (float*)d_out;

    prep_q<<<(B * H / 2 + 255) / 256, 256>>>(q);
    mm_tc<<<KQ / MROWS, TCTHREADS, SMEM_TC>>>(fq, lab_q, clu_q, lab_k, clu_k);
    pos_part<<<dim3(2, B), 256>>>();
    for (int pass = 0; pass < 3; ++pass) {
        int shift = 8 + pass * 8;
        rs_hist<<<dim3(32, B), 256>>>(shift, pass & 1, pass == 0, topk);
        rs_scan<<<B, 256>>>();
        rs_scatter<<<dim3(32, B), 256>>>(shift, pass & 1);
    }
    write_k<<<dim3(4, 320), 256>>>(out);
}

// round 16
// speedup vs baseline: 1.0500x; 1.0500x over previous
#include <cuda_runtime.h>
#include <cstdint>
#include <cstddef>

#define FULLMASK 0xFFFFFFFFu

// ---------------- problem constants ------------------------------------------
constexpr int B  = 32;
constexpr int H  = 768;
constexpr int KQ = 131072;

// ---------------- mma.sync matmul tiling --------------------------------------
constexpr int MROWS = 128;
constexpr int NCHT  = H / 64;
constexpr int TCTHREADS = 128;
constexpr int AST   = 36;
constexpr int SM_A     = 0;
constexpr int SM_B     = 36864;
constexpr int SM_CLB   = 46080;
constexpr int SM_LBB   = 46208;
constexpr int SMEM_TC  = 46336;
constexpr int SM_SIMS  = 0;
constexpr int SM_STAGE = 16896;
constexpr int SM_WC    = 33280;
constexpr int SM_LOFS  = 34304;
constexpr int SM_BASE  = 34560;
constexpr int SM_CNT   = 34816;

// ---------------- scratch ----------------------------------------------------
__device__ unsigned int g_bufP [(size_t)B * KQ];
__device__ unsigned int g_bufN0[(size_t)B * KQ];
__device__ unsigned int g_bufN1[(size_t)B * KQ];
__device__ unsigned int g_histA[B * 8192];
__device__ int g_cntP[B];
__device__ int g_cntN[B];
__device__ int g_pmm[2];
__device__ unsigned int g_posPart[B * 40];    // 4 chunks x 10 per row
__device__ unsigned int g_qhi[B * H / 2];
__device__ unsigned int g_qlo[B * H / 2];

__device__ __forceinline__ unsigned int keyOf(float f) {
    unsigned int u = __float_as_uint(f);
    return (u & 0x80000000u) ? u : (~u & 0x7FFFFFFFu);
}
__device__ __forceinline__ float valOf(unsigned int d) {
    unsigned int u = (d & 0x80000000u) ? d : (~d & 0x7FFFFFFFu);
    return __uint_as_float(u);
}
__device__ __forceinline__ uint32_t smem_to_u32(const void* p) {
    uint32_t a;
    asm("{ .reg .u64 t; cvta.to.shared.u64 t, %1; cvt.u32.u64 %0, t; }" : "=r"(a) : "l"(p));
    return a;
}

#define CVT_BF16X2(res, e0, e1) \
    asm("cvt.rn.satfinite.bf16x2.f32 %0, %1, %2;" : "=r"(res) : "f"(e1), "f"(e0))

__device__ __forceinline__ void mma_bf16(float* d, const unsigned* a, const unsigned* b) {
    asm volatile("mma.sync.aligned.m16n8k16.row.col.f32.bf16.bf16.f32 "
                 "{%0,%1,%2,%3}, {%4,%5,%6,%7}, {%8,%9}, {%0,%1,%2,%3};"
                 : "+f"(d[0]), "+f"(d[1]), "+f"(d[2]), "+f"(d[3])
                 : "r"(a[0]), "r"(a[1]), "r"(a[2]), "r"(a[3]),
                   "r"(b[0]), "r"(b[1]));
}
__device__ __forceinline__ void ldsm_x4(unsigned* r, uint32_t addr) {
    asm volatile("ldmatrix.sync.aligned.m8n8.x4.shared.b16 {%0,%1,%2,%3}, [%4];"
                 : "=r"(r[0]), "=r"(r[1]), "=r"(r[2]), "=r"(r[3]) : "r"(addr));
}

// ---------------- kernel: zero counters + split queries into bf16 hi/lo --------
__global__ void prep_q(const float* __restrict__ q) {
    int w = blockIdx.x * 256 + threadIdx.x;
    if (w < B) { g_cntP[w] = 0; g_cntN[w] = 0; }
    if (w >= B * H / 2) return;
    float x0 = q[2 * w], x1 = q[2 * w + 1];
    unsigned int whi; CVT_BF16X2(whi, x0, x1);
    float h0 = __uint_as_float(whi << 16);
    float h1 = __uint_as_float(whi & 0xFFFF0000u);
    unsigned int wlo; CVT_BF16X2(wlo, x0 - h0, x1 - h1);
    g_qhi[w] = whi;
    g_qlo[w] = wlo;
}

// ---------------- kernel 1: mma.sync + ldmatrix matmul + mask partition --------
__global__ __launch_bounds__(TCTHREADS, 2)
void mm_tc(const float* __restrict__ fq,
           const int* __restrict__ lab_q, const int* __restrict__ clu_q,
           const int* __restrict__ lab_k, const int* __restrict__ clu_k)
{
    extern __shared__ char sm[];
    const uint32_t smb = smem_to_u32(sm);
    const int t = threadIdx.x;
    const int w = t >> 5, lane = t & 31;
    const int g = lane >> 2, c4 = lane & 3;
    const int k0 = blockIdx.x * MROWS;

    int* s_clb = (int*)(sm + SM_CLB);
    int* s_lbb = (int*)(sm + SM_LBB);
    if (t < 32) { s_clb[t] = clu_q[t]; s_lbb[t] = lab_q[t]; }

    unsigned int* smAh = (unsigned int*)(sm + SM_A);
    unsigned int* smAl = smAh + MROWS * AST;
    unsigned int* smBh = (unsigned int*)(sm + SM_B);
    unsigned int* smBl = smBh + 32 * AST;

    uint32_t aAddr[2][2];
    {
        int row = w * 32 + (lane & 7) + ((lane >> 3) & 1) * 8;
        int word = ((lane >> 4) & 1) * 4;
        #pragma unroll
        for (int mt = 0; mt < 2; mt++) {
            uint32_t off = (uint32_t)(((row + mt * 16) * AST + word) * 4);
            aAddr[0][mt] = smb + SM_A + off;
            aAddr[1][mt] = smb + SM_A + 18432u + off;
        }
    }
    uint32_t bAddr[2][2];
    {
        int row = (lane & 7) + ((lane >> 4) & 1) * 8;
        int word = ((lane >> 3) & 1) * 4;
        #pragma unroll
        for (int ntp = 0; ntp < 2; ntp++) {
            uint32_t off = (uint32_t)(((row + ntp * 16) * AST + word) * 4);
            bAddr[0][ntp] = smb + SM_B + off;
            bAddr[1][ntp] = smb + SM_B + 4608u + off;
        }
    }

    const float4* gA = (const float4*)(fq + (size_t)(k0 + t) * H);

    float4 areg[16];
    unsigned int bhr[8], blr[8];

    auto loadChunk = [&](int c) {
        const float4* p = gA + c * 16;
        #pragma unroll
        for (int ii = 0; ii < 16; ii++) areg[ii] = p[ii];
        #pragma unroll
        for (int ps = 0; ps < 8; ps++) {
            int idx = ps * TCTHREADS + t;
            int n = idx >> 5, wd = idx & 31;
            bhr[ps] = g_qhi[n * (H / 2) + c * 32 + wd];
            blr[ps] = g_qlo[n * (H / 2) + c * 32 + wd];
        }
    };
    auto storeChunk = [&]() {
        #pragma unroll
        for (int ii = 0; ii < 16; ii += 2) {
            float4 v0 = areg[ii], v1 = areg[ii + 1];
            unsigned int h0, h1, h2, h3, l0, l1, l2, l3;
            CVT_BF16X2(h0, v0.x, v0.y);
            CVT_BF16X2(h1, v0.z, v0.w);
            CVT_BF16X2(h2, v1.x, v1.y);
            CVT_BF16X2(h3, v1.z, v1.w);
            float r0 = v0.x - __uint_as_float(h0 << 16);
            float r1 = v0.y - __uint_as_float(h0 & 0xFFFF0000u);
            float r2 = v0.z - __uint_as_float(h1 << 16);
            float r3 = v0.w - __uint_as_float(h1 & 0xFFFF0000u);
            float r4 = v1.x - __uint_as_float(h2 << 16);
            float r5 = v1.y - __uint_as_float(h2 & 0xFFFF0000u);
            float r6 = v1.z - __uint_as_float(h3 << 16);
            float r7 = v1.w - __uint_as_float(h3 & 0xFFFF0000u);
            CVT_BF16X2(l0, r0, r1);
            CVT_BF16X2(l1, r2, r3);
            CVT_BF16X2(l2, r4, r5);
            CVT_BF16X2(l3, r6, r7);
            *(uint4*)&smAh[t * AST + 2 * ii] = make_uint4(h0, h1, h2, h3);
            *(uint4*)&smAl[t * AST + 2 * ii] = make_uint4(l0, l1, l2, l3);
        }
        #pragma unroll
        for (int ps = 0; ps < 8; ps++) {
            int idx = ps * TCTHREADS + t;
            int n = idx >> 5, wd = idx & 31;
            smBh[n * AST + wd] = bhr[ps];
            smBl[n * AST + wd] = blr[ps];
        }
    };

    float acc[2][4][4];
    #pragma unroll
    for (int mt = 0; mt < 2; mt++)
        #pragma unroll
        for (int nt = 0; nt < 4; nt++)
            #pragma unroll
            for (int r = 0; r < 4; r++) acc[mt][nt][r] = 0.0f;

    loadChunk(0);
    for (int c = 0; c < NCHT; c++) {
        if (c > 0) __syncthreads();
        storeChunk();
        if (c + 1 < NCHT) loadChunk(c + 1);
        __syncthreads();

        #pragma unroll
        for (int ks = 0; ks < 4; ks++) {
            const uint32_t kb = (uint32_t)(ks * 32);
            unsigned int ah[2][4], al[2][4], bh[4][2], bl[4][2];
            #pragma unroll
            for (int mt = 0; mt < 2; mt++) {
                ldsm_x4(ah[mt], aAddr[0][mt] + kb);
                ldsm_x4(al[mt], aAddr[1][mt] + kb);
            }
            #pragma unroll
            for (int ntp = 0; ntp < 2; ntp++) {
                unsigned int rh[4], rl[4];
                ldsm_x4(rh, bAddr[0][ntp] + kb);
                ldsm_x4(rl, bAddr[1][ntp] + kb);
                bh[2 * ntp][0] = rh[0]; bh[2 * ntp][1] = rh[1];
                bh[2 * ntp + 1][0] = rh[2]; bh[2 * ntp + 1][1] = rh[3];
                bl[2 * ntp][0] = rl[0]; bl[2 * ntp][1] = rl[1];
                bl[2 * ntp + 1][0] = rl[2]; bl[2 * ntp + 1][1] = rl[3];
            }
            #pragma unroll
            for (int mt = 0; mt < 2; mt++)
                #pragma unroll
                for (int nt = 0; nt < 4; nt++)
                    mma_bf16(acc[mt][nt], ah[mt], bh[nt]);
            #pragma unroll
            for (int mt = 0; mt < 2; mt++)
                #pragma unroll
                for (int nt = 0; nt < 4; nt++)
                    mma_bf16(acc[mt][nt], ah[mt], bl[nt]);
            #pragma unroll
            for (int mt = 0; mt < 2; mt++)
                #pragma unroll
                for (int nt = 0; nt < 4; nt++)
                    mma_bf16(acc[mt][nt], al[mt], bh[nt]);
        }
    }
    __syncthreads();

    float* sims = (float*)(sm + SM_SIMS);
    #pragma unroll
    for (int mt = 0; mt < 2; mt++) {
        int r0 = w * 32 + mt * 16 + g;
        #pragma unroll
        for (int nt = 0; nt < 4; nt++) {
            int cb = nt * 8 + 2 * c4;
            sims[r0 * 33 + cb]           = acc[mt][nt][0];
            sims[r0 * 33 + cb + 1]       = acc[mt][nt][1];
            sims[(r0 + 8) * 33 + cb]     = acc[mt][nt][2];
            sims[(r0 + 8) * 33 + cb + 1] = acc[mt][nt][3];
        }
    }
    __syncthreads();

    unsigned int* stage = (unsigned int*)(sm + SM_STAGE);
    int* s_wc   = (int*)(sm + SM_WC);
    int* s_lofs = (int*)(sm + SM_LOFS);
    int* s_base = (int*)(sm + SM_BASE);
    int* s_cnt  = (int*)(sm + SM_CNT);

    int clk = clu_k[k0 + t];
    int lbk = lab_k[k0 + t];
    float myS[32];
    #pragma unroll
    for (int b = 0; b < 32; b++) myS[b] = sims[t * 33 + b];

    #pragma unroll
    for (int b = 0; b < 32; b++) {
        int neg = (clk == s_clb[b]) != (lbk == s_lbb[b]);
        unsigned int mask = __ballot_sync(FULLMASK, neg);
        if (lane == 0) {
            int cn = __popc(mask);
            s_wc[(b * 2 + 1) * 4 + w] = cn;
            s_wc[(b * 2) * 4 + w] = 32 - cn;
        }
    }
    __syncthreads();
    if (t < 64) {
        int run = 0, st[4];
        #pragma unroll
        for (int ww = 0; ww < 4; ww++) { st[ww] = run; run += s_wc[t * 4 + ww]; }
        #pragma unroll
        for (int ww = 0; ww < 4; ww++) s_wc[t * 4 + ww] = st[ww];
        s_cnt[t] = run;
        int b = t >> 1, neg = t & 1;
        s_base[t] = run ? atomicAdd(neg ? &g_cntN[b] : &g_cntP[b], run) : 0;
    }
    __syncthreads();
    if (t == 0) {
        int run = 0;
        for (int s = 0; s < 64; s++) { s_lofs[s] = run; run += s_cnt[s]; }
    }
    __syncthreads();
    {
        unsigned int below = (1u << lane) - 1u;
        #pragma unroll
        for (int b = 0; b < 32; b++) {
            int neg = (clk == s_clb[b]) != (lbk == s_lbb[b]);
            unsigned int mask = __ballot_sync(FULLMASK, neg);
            int seg = b * 2 + neg;
            int rank = neg ? __popc(mask & below) : __popc(~mask & below);
            stage[s_lofs[seg] + s_wc[seg * 4 + w] + rank] = keyOf(myS[b]);
        }
    }
    __syncthreads();
    for (int s = w * 16; s < w * 16 + 16; s++) {
        int cnt = s_cnt[s];
        int b = s >> 1, neg = s & 1;
        unsigned int* dst = (neg ? g_bufN0 : g_bufP) + (size_t)b * KQ + s_base[s];
        const unsigned int* srcP = stage + s_lofs[s];
        for (int i = lane; i < cnt; i += 32) dst[i] = srcP[i];
    }
}

// ---------------- per-pass histogram, MLP-16 prefetch (+ fused minmax) ---------
__global__ void rs_hist(int shift, int srcSel, int doMinmax,
                        const int* __restrict__ topk) {
    int chunk = blockIdx.x, row = blockIdx.y;
    int t = threadIdx.x;
    if (doMinmax && chunk == 0 && row == 0 && t < 32) {
        int cp = g_cntP[t], cn = g_cntN[t];
        #pragma unroll
        for (int off = 16; off; off >>= 1) {
            cp = min(cp, __shfl_down_sync(FULLMASK, cp, off));
            cn = min(cn, __shfl_down_sync(FULLMASK, cn, off));
        }
        if (t == 0) { g_pmm[0] = min(cp, topk[0]); g_pmm[1] = cn; }
    }
    int n = g_cntN[row];
    int s0 = chunk * 4096;
    __shared__ int h[256];
    h[t] = 0;
    __syncthreads();
    if (s0 < n) {
        const unsigned int* in = (srcSel ? g_bufN1 : g_bufN0) + (size_t)row * KQ + s0;
        int lim = min(4096, n - s0);
        // prefetch 16 independent loads (MLP=16), then replay for atomics
        unsigned int keys[16];
        #pragma unroll
        for (int j = 0; j < 16; j++) {
            int i = j * 256 + t;
            keys[j] = (i < lim) ? in[i] : 0u;
        }
        #pragma unroll
        for (int j = 0; j < 16; j++) {
            int i = j * 256 + t;
            if (i < lim) atomicAdd(&h[(keys[j] >> shift) & 255], 1);
        }
    }
    __syncthreads();
    g_histA[row * 8192 + t * 32 + chunk] = h[t];
}

// ---------------- scan ---------------------------------------------------------
__global__ void rs_scan() {
    int row = blockIdx.x;
    unsigned int* a = g_histA + row * 8192;
    int t = threadIdx.x;
    int v[32]; int sum = 0;
    int base = t * 32;
    #pragma unroll
    for (int i = 0; i < 32; i++) { v[i] = (int)a[base + i]; sum += v[i]; }
    __shared__ int ps[256];
    ps[t] = sum;
    __syncthreads();
    for (int off = 1; off < 256; off <<= 1) {
        int x = (t >= off) ? ps[t - off] : 0;
        __syncthreads();
        ps[t] += x;
        __syncthreads();
    }
    int run = (t > 0) ? ps[t - 1] : 0;
    #pragma unroll
    for (int i = 0; i < 32; i++) { int tmp = v[i]; a[base + i] = (unsigned)run; run += tmp; }
}

// ---------------- top-10 of positives (4 blocks/row, 64 keys/thread) -----------
__device__ __forceinline__ void insert10(unsigned int (&best)[10], unsigned int k) {
    if (k < best[9]) {
        int j = 9;
        #pragma unroll
        for (int s = 0; s < 9; s++) {
            if (j > 0 && best[j - 1] > k) { best[j] = best[j - 1]; j--; }
        }
        best[j] = k;
    }
}

__global__ void pos_part() {
    int c = blockIdx.x, row = blockIdx.y;   // c in {0..3}
    int n = g_cntP[row];
    int per = (n + 3) >> 2;
    int s = c * per, e = min(s + per, n);
    const unsigned int* src = g_bufP + (size_t)row * KQ;
    int t = threadIdx.x;
    int w = t >> 5, lane = t & 31;
    unsigned int best[10];
    #pragma unroll
    for (int i = 0; i < 10; i++) best[i] = 0xFFFFFFFFu;
    for (int base = s; base < e; base += 2048) {
        unsigned int k[8];
        #pragma unroll
        for (int qn = 0; qn < 8; qn++) {
            int idx = base + qn * 256 + t;
            k[qn] = (idx < e) ? src[idx] : 0xFFFFFFFFu;
        }
        #pragma unroll
        for (int qn = 0; qn < 8; qn++) insert10(best, k[qn]);
    }
    __shared__ unsigned int sh[8 * 10];
    #pragma unroll
    for (int r = 0; r < 10; r++) {
        unsigned int cand = best[0];
        unsigned int wmin = cand;
        #pragma unroll
        for (int off = 16; off; off >>= 1)
            wmin = min(wmin, __shfl_xor_sync(FULLMASK, wmin, off));
        unsigned int bal = __ballot_sync(FULLMASK, cand == wmin);
        int leader = __ffs(bal) - 1;
        if (lane == leader) {
            #pragma unroll
            for (int i = 0; i < 9; i++) best[i] = best[i + 1];
            best[9] = 0xFFFFFFFFu;
        }
        if (lane == 0) sh[w * 10 + r] = wmin;
    }
    __syncthreads();
    if (w == 0) {
        int head = 0;
        for (int r = 0; r < 10; r++) {
            unsigned int cand = (lane < 8) ? sh[lane * 10 + head] : 0xFFFFFFFFu;
            unsigned int wmin = cand;
            #pragma unroll
            for (int off = 16; off; off >>= 1)
                wmin = min(wmin, __shfl_xor_sync(FULLMASK, wmin, off));
            unsigned int bal = __ballot_sync(FULLMASK, cand == wmin && lane < 8);
            int leader = __ffs(bal) - 1;
            if (lane == leader) head++;
            if (lane == 0) g_posPart[row * 40 + c * 10 + r] = wmin;
        }
    }
}

// ---------------- radix scatter (3 passes) -------------------------------------
__global__ __launch_bounds__(256)
void rs_scatter(int shift, int srcSel) {
    int chunk = blockIdx.x, row = blockIdx.y;
    int n = g_cntN[row];
    int s0 = chunk * 4096;
    if (s0 >= n) return;
    const unsigned int* in  = (srcSel ? g_bufN1 : g_bufN0) + (size_t)row * KQ;
    unsigned int*       out = (srcSel ? g_bufN0 : g_bufN1) + (size_t)row * KQ;
    const unsigned int* Hb  = g_histA + row * 8192;

    __shared__ unsigned int sKeys[4096];
    __shared__ int wh[8 * 256];
    __shared__ int gb[256];
    __shared__ int lofs[256];
    __shared__ int ps[256];

    int t = threadIdx.x;
    int w = t >> 5, lane = t & 31;
    int wbase = s0 + 512 * w;

    unsigned int myKeys[16];
    #pragma unroll
    for (int j = 0; j < 16; j++) {
        int idx = wbase + 32 * j + lane;
        myKeys[j] = (idx < n) ? in[idx] : 0xFFFFFFFFu;
    }

    #pragma unroll
    for (int qq = 0; qq < 8; qq++) wh[qq * 256 + t] = 0;
    __syncthreads();

    #pragma unroll
    for (int j = 0; j < 16; j++) {
        int idx = wbase + 32 * j + lane;
        if (idx < n) atomicAdd(&wh[w * 256 + ((myKeys[j] >> shift) & 255)], 1);
    }
    __syncthreads();

    int tot = 0; int wstart[8];
    #pragma unroll
    for (int ww = 0; ww < 8; ww++) { wstart[ww] = tot; tot += wh[ww * 256 + t]; }
    ps[t] = tot;
    gb[t] = (int)Hb[t * 32 + chunk];
    __syncthreads();
    for (int off = 1; off < 256; off <<= 1) {
        int x = (t >= off) ? ps[t - off] : 0;
        __syncthreads();
        ps[t] += x;
        __syncthreads();
    }
    int lo = ps[t] - tot;
    lofs[t] = lo;
    #pragma unroll
    for (int ww = 0; ww < 8; ww++) wh[ww * 256 + t] = lo + wstart[ww];
    __syncthreads();

    #pragma unroll
    for (int j = 0; j < 16; j++) {
        int idx = wbase + 32 * j + lane;
        bool val = idx < n;
        unsigned int key = myKeys[j];
        int d = (key >> shift) & 255;
        unsigned int vm = __ballot_sync(FULLMASK, val);
        unsigned int peers = FULLMASK;
        #pragma unroll
        for (int bb = 0; bb < 8; ++bb) {
            unsigned int vote = __ballot_sync(FULLMASK, (d >> bb) & 1);
            peers &= ((d >> bb) & 1) ? vote : ~vote;
        }
        peers &= vm;
        int rank = __popc(peers & ((1u << lane) - 1u));
        int leader = peers ? (__ffs(peers) - 1) : 0;
        int basePos = 0;
        if (val && rank == 0) basePos = atomicAdd(&wh[w * 256 + d], __popc(peers));
        basePos = __shfl_sync(FULLMASK, basePos, leader);
        if (val) sKeys[basePos + rank] = key;
    }
    __syncthreads();

    int lim = min(4096, n - s0);
    for (int pos = t; pos < lim; pos += 256) {
        unsigned int key = sKeys[pos];
        int d = (key >> shift) & 255;
        out[gb[d] + (pos - lofs[d])] = key;
    }
}

// ---------------- writer (final sorted negatives in g_bufN1) -------------------
// c==0 threads do the pos merge inline: p-th smallest of the 4x10 partial lists.
__global__ void write_k(float* __restrict__ out) {
    int r = blockIdx.y;
    unsigned int pm = (unsigned int)g_pmm[0];
    unsigned int nm = (unsigned int)g_pmm[1];
    if ((unsigned)r >= 32u * pm) return;
    unsigned int width = nm + 1u;
    unsigned int b = (unsigned)r / pm;
    unsigned int p = (unsigned)r - b * pm;
    const float invT = 1.0f / 0.07f;
    size_t rowBase = (size_t)r * width;
    const unsigned int* negRow = g_bufN1 + (size_t)b * KQ;

    unsigned int qlen = (width + 3u) >> 2;
    unsigned int c = blockIdx.x * qlen + threadIdx.x;
    unsigned int cend = min((blockIdx.x + 1u) * qlen, width);
    if (c >= cend) return;
    if (c == 0u) {
        const unsigned int* parts = g_posPart + b * 40;
        unsigned int res = 0u;
        for (int j = 0; j < 40; j++) {
            unsigned int xj = parts[j];
            int rank = 0;
            #pragma unroll 8
            for (int i = 0; i < 40; i++) {
                unsigned int xi = parts[i];
                rank += (xi < xj) || (xi == xj && i < j);
            }
            if (rank == (int)p) res = xj;
        }
        out[rowBase] = valOf(res) * invT;
        c += 256u;
        if (c >= cend) return;
    }
    unsigned int num = p * nm + (c - 1u);
    unsigned int qi = num / pm;
    unsigned int rem = num - qi * pm;
    unsigned int d256 = 256u / pm;
    unsigned int r256 = 256u - d256 * pm;
    while (c < cend) {
        out[rowBase + c] = valOf(negRow[qi]) * invT;
        c += 256u;
        qi += d256;
        rem += r256;
        if (rem >= pm) { rem -= pm; qi += 1u; }
    }
}

// ---------------- launcher ----------------------------------------------------
extern "C" void kernel_launch(void* const* d_in, const int* in_sizes, int n_in,
                              void* d_out, int out_size) {
    const float* q     = (const float*)d_in[0];
    const float* fq    = (const float*)d_in[1];
    const int* lab_q   = (const int*)d_in[2];
    const int* clu_q   = (const int*)d_in[3];
    const int* lab_k   = (const int*)d_in[4];
    const int* clu_k   = (const int*)d_in[5];
    const int* topk    = (const int*)d_in[6];
    float* out = (float*)d_out;

    prep_q<<<(B * H / 2 + 255) / 256, 256>>>(q);
    mm_tc<<<KQ / MROWS, TCTHREADS, SMEM_TC>>>(fq, lab_q, clu_q, lab_k, clu_k);
    pos_part<<<dim3(4, B), 256>>>();
    for (int pass = 0; pass < 3; ++pass) {
        int shift = 8 + pass * 8;
        rs_hist<<<dim3(32, B), 256>>>(shift, pass & 1, pass == 0, topk);
        rs_scan<<<B, 256>>>();
        rs_scatter<<<dim3(32, B), 256>>>(shift, pass & 1);
    }
    write_k<<<dim3(4, 320), 256>>>(out);
}

// round 17
// speedup vs baseline: 1.0752x; 1.0240x over previous
#include <cuda_runtime.h>
#include <cstdint>
#include <cstddef>

#define FULLMASK 0xFFFFFFFFu

// ---------------- problem constants ------------------------------------------
constexpr int B  = 32;
constexpr int H  = 768;
constexpr int KQ = 131072;

// ---------------- mma.sync matmul tiling --------------------------------------
constexpr int MROWS = 128;
constexpr int NCHT  = H / 64;
constexpr int TCTHREADS = 128;
constexpr int AST   = 36;
// double-buffered smem layout (bytes)
constexpr int ABUF    = 36864;                 // Ah(18432)+Al(18432) per buffer
constexpr int BBUF    = 9216;                  // Bh(4608)+Bl(4608) per buffer
constexpr int SM_A    = 0;                     // 2 x ABUF = 73728
constexpr int SM_B    = 73728;                 // 2 x BBUF = 18432 -> 92160
constexpr int SM_CLB  = 92160;
constexpr int SM_LBB  = 92288;
constexpr int SMEM_TC = 92416;
// epilogue reuse (inside A region):
constexpr int SM_SIMS  = 0;                    // 128*33 floats = 16896
constexpr int SM_STAGE = 16896;                // 4096 uints
constexpr int SM_WC    = 33280;
constexpr int SM_LOFS  = 34304;
constexpr int SM_BASE  = 34560;
constexpr int SM_CNT   = 34816;

// ---------------- scratch ----------------------------------------------------
__device__ unsigned int g_bufP [(size_t)B * KQ];
__device__ unsigned int g_bufN0[(size_t)B * KQ];
__device__ unsigned int g_bufN1[(size_t)B * KQ];
__device__ unsigned int g_histA[B * 8192];
__device__ int g_cntP[B];
__device__ int g_cntN[B];
__device__ int g_pmm[2];
__device__ unsigned int g_posPart[B * 40];    // 4 chunks x 10 per row
__device__ unsigned int g_qhi[B * H / 2];
__device__ unsigned int g_qlo[B * H / 2];

__device__ __forceinline__ unsigned int keyOf(float f) {
    unsigned int u = __float_as_uint(f);
    return (u & 0x80000000u) ? u : (~u & 0x7FFFFFFFu);
}
__device__ __forceinline__ float valOf(unsigned int d) {
    unsigned int u = (d & 0x80000000u) ? d : (~d & 0x7FFFFFFFu);
    return __uint_as_float(u);
}
__device__ __forceinline__ uint32_t smem_to_u32(const void* p) {
    uint32_t a;
    asm("{ .reg .u64 t; cvta.to.shared.u64 t, %1; cvt.u32.u64 %0, t; }" : "=r"(a) : "l"(p));
    return a;
}

#define CVT_BF16X2(res, e0, e1) \
    asm("cvt.rn.satfinite.bf16x2.f32 %0, %1, %2;" : "=r"(res) : "f"(e1), "f"(e0))

__device__ __forceinline__ void mma_bf16(float* d, const unsigned* a, const unsigned* b) {
    asm volatile("mma.sync.aligned.m16n8k16.row.col.f32.bf16.bf16.f32 "
                 "{%0,%1,%2,%3}, {%4,%5,%6,%7}, {%8,%9}, {%0,%1,%2,%3};"
                 : "+f"(d[0]), "+f"(d[1]), "+f"(d[2]), "+f"(d[3])
                 : "r"(a[0]), "r"(a[1]), "r"(a[2]), "r"(a[3]),
                   "r"(b[0]), "r"(b[1]));
}
__device__ __forceinline__ void ldsm_x4(unsigned* r, uint32_t addr) {
    asm volatile("ldmatrix.sync.aligned.m8n8.x4.shared.b16 {%0,%1,%2,%3}, [%4];"
                 : "=r"(r[0]), "=r"(r[1]), "=r"(r[2]), "=r"(r[3]) : "r"(addr));
}

// ---------------- kernel: zero counters + split queries into bf16 hi/lo --------
__global__ void prep_q(const float* __restrict__ q) {
    int w = blockIdx.x * 256 + threadIdx.x;
    if (w < B) { g_cntP[w] = 0; g_cntN[w] = 0; }
    if (w >= B * H / 2) return;
    float x0 = q[2 * w], x1 = q[2 * w + 1];
    unsigned int whi; CVT_BF16X2(whi, x0, x1);
    float h0 = __uint_as_float(whi << 16);
    float h1 = __uint_as_float(whi & 0xFFFF0000u);
    unsigned int wlo; CVT_BF16X2(wlo, x0 - h0, x1 - h1);
    g_qhi[w] = whi;
    g_qlo[w] = wlo;
}

// ---------------- kernel 1: pipelined mma.sync matmul + mask partition ---------
__global__ __launch_bounds__(TCTHREADS, 2)
void mm_tc(const float* __restrict__ fq,
           const int* __restrict__ lab_q, const int* __restrict__ clu_q,
           const int* __restrict__ lab_k, const int* __restrict__ clu_k)
{
    extern __shared__ char sm[];
    const uint32_t smb = smem_to_u32(sm);
    const int t = threadIdx.x;
    const int w = t >> 5, lane = t & 31;
    const int g = lane >> 2, c4 = lane & 3;
    const int k0 = blockIdx.x * MROWS;

    int* s_clb = (int*)(sm + SM_CLB);
    int* s_lbb = (int*)(sm + SM_LBB);
    if (t < 32) { s_clb[t] = clu_q[t]; s_lbb[t] = lab_q[t]; }

    // ldmatrix per-lane base addresses (buffer 0; buffer 1 = +ABUF/+BBUF)
    uint32_t aAddr[2][2];   // [hl][mt]
    {
        int row = w * 32 + (lane & 7) + ((lane >> 3) & 1) * 8;
        int word = ((lane >> 4) & 1) * 4;
        #pragma unroll
        for (int mt = 0; mt < 2; mt++) {
            uint32_t off = (uint32_t)(((row + mt * 16) * AST + word) * 4);
            aAddr[0][mt] = smb + SM_A + off;
            aAddr[1][mt] = smb + SM_A + 18432u + off;
        }
    }
    uint32_t bAddr[2][2];   // [hl][ntp]
    {
        int row = (lane & 7) + ((lane >> 4) & 1) * 8;
        int word = ((lane >> 3) & 1) * 4;
        #pragma unroll
        for (int ntp = 0; ntp < 2; ntp++) {
            uint32_t off = (uint32_t)(((row + ntp * 16) * AST + word) * 4);
            bAddr[0][ntp] = smb + SM_B + off;
            bAddr[1][ntp] = smb + SM_B + 4608u + off;
        }
    }

    const float4* gA = (const float4*)(fq + (size_t)(k0 + t) * H);

    float4 areg[16];
    unsigned int bhr[8], blr[8];

    auto loadChunk = [&](int c) {
        const float4* p = gA + c * 16;
        #pragma unroll
        for (int ii = 0; ii < 16; ii++) areg[ii] = p[ii];
        #pragma unroll
        for (int ps = 0; ps < 8; ps++) {
            int idx = ps * TCTHREADS + t;
            int n = idx >> 5, wd = idx & 31;
            bhr[ps] = g_qhi[n * (H / 2) + c * 32 + wd];
            blr[ps] = g_qlo[n * (H / 2) + c * 32 + wd];
        }
    };
    auto storeChunk = [&](int bi) {
        unsigned int* smAh = (unsigned int*)(sm + SM_A + bi * ABUF);
        unsigned int* smAl = smAh + MROWS * AST;          // +18432 B
        unsigned int* smBh = (unsigned int*)(sm + SM_B + bi * BBUF);
        unsigned int* smBl = smBh + 32 * AST;             // +4608 B
        #pragma unroll
        for (int ii = 0; ii < 16; ii += 2) {
            float4 v0 = areg[ii], v1 = areg[ii + 1];
            unsigned int h0, h1, h2, h3, l0, l1, l2, l3;
            CVT_BF16X2(h0, v0.x, v0.y);
            CVT_BF16X2(h1, v0.z, v0.w);
            CVT_BF16X2(h2, v1.x, v1.y);
            CVT_BF16X2(h3, v1.z, v1.w);
            float r0 = v0.x - __uint_as_float(h0 << 16);
            float r1 = v0.y - __uint_as_float(h0 & 0xFFFF0000u);
            float r2 = v0.z - __uint_as_float(h1 << 16);
            float r3 = v0.w - __uint_as_float(h1 & 0xFFFF0000u);
            float r4 = v1.x - __uint_as_float(h2 << 16);
            float r5 = v1.y - __uint_as_float(h2 & 0xFFFF0000u);
            float r6 = v1.z - __uint_as_float(h3 << 16);
            float r7 = v1.w - __uint_as_float(h3 & 0xFFFF0000u);
            CVT_BF16X2(l0, r0, r1);
            CVT_BF16X2(l1, r2, r3);
            CVT_BF16X2(l2, r4, r5);
            CVT_BF16X2(l3, r6, r7);
            *(uint4*)&smAh[t * AST + 2 * ii] = make_uint4(h0, h1, h2, h3);
            *(uint4*)&smAl[t * AST + 2 * ii] = make_uint4(l0, l1, l2, l3);
        }
        #pragma unroll
        for (int ps = 0; ps < 8; ps++) {
            int idx = ps * TCTHREADS + t;
            int n = idx >> 5, wd = idx & 31;
            smBh[n * AST + wd] = bhr[ps];
            smBl[n * AST + wd] = blr[ps];
        }
    };

    float acc[2][4][4];
    #pragma unroll
    for (int mt = 0; mt < 2; mt++)
        #pragma unroll
        for (int nt = 0; nt < 4; nt++)
            #pragma unroll
            for (int r = 0; r < 4; r++) acc[mt][nt][r] = 0.0f;

    // pipeline prologue: buf0 <- chunk 0; regs <- chunk 1
    loadChunk(0);
    storeChunk(0);
    loadChunk(1);
    __syncthreads();

    for (int c = 0; c < NCHT; c++) {
        const int bi = c & 1;
        const uint32_t aoff = (uint32_t)(bi * ABUF);
        const uint32_t boff = (uint32_t)(bi * BBUF);

        // stage next chunk into the other buffer; prefetch chunk c+2
        if (c + 1 < NCHT) {
            storeChunk(1 - bi);
            if (c + 2 < NCHT) loadChunk(c + 2);
        }

        // math on buffer bi (chunk c) — interleaves with the stores above
        #pragma unroll
        for (int ks = 0; ks < 4; ks++) {
            const uint32_t kb = (uint32_t)(ks * 32);
            unsigned int ah[2][4], al[2][4], bh[4][2], bl[4][2];
            #pragma unroll
            for (int mt = 0; mt < 2; mt++) {
                ldsm_x4(ah[mt], aAddr[0][mt] + aoff + kb);
                ldsm_x4(al[mt], aAddr[1][mt] + aoff + kb);
            }
            #pragma unroll
            for (int ntp = 0; ntp < 2; ntp++) {
                unsigned int rh[4], rl[4];
                ldsm_x4(rh, bAddr[0][ntp] + boff + kb);
                ldsm_x4(rl, bAddr[1][ntp] + boff + kb);
                bh[2 * ntp][0] = rh[0]; bh[2 * ntp][1] = rh[1];
                bh[2 * ntp + 1][0] = rh[2]; bh[2 * ntp + 1][1] = rh[3];
                bl[2 * ntp][0] = rl[0]; bl[2 * ntp][1] = rl[1];
                bl[2 * ntp + 1][0] = rl[2]; bl[2 * ntp + 1][1] = rl[3];
            }
            #pragma unroll
            for (int mt = 0; mt < 2; mt++)
                #pragma unroll
                for (int nt = 0; nt < 4; nt++)
                    mma_bf16(acc[mt][nt], ah[mt], bh[nt]);
            #pragma unroll
            for (int mt = 0; mt < 2; mt++)
                #pragma unroll
                for (int nt = 0; nt < 4; nt++)
                    mma_bf16(acc[mt][nt], ah[mt], bl[nt]);
            #pragma unroll
            for (int mt = 0; mt < 2; mt++)
                #pragma unroll
                for (int nt = 0; nt < 4; nt++)
                    mma_bf16(acc[mt][nt], al[mt], bh[nt]);
        }
        __syncthreads();   // buf(1-bi) stores visible; buf(bi) safe to overwrite next iter
    }

    // ---- write sims fragments to smem [row][33] ------------------------------
    float* sims = (float*)(sm + SM_SIMS);
    #pragma unroll
    for (int mt = 0; mt < 2; mt++) {
        int r0 = w * 32 + mt * 16 + g;
        #pragma unroll
        for (int nt = 0; nt < 4; nt++) {
            int cb = nt * 8 + 2 * c4;
            sims[r0 * 33 + cb]           = acc[mt][nt][0];
            sims[r0 * 33 + cb + 1]       = acc[mt][nt][1];
            sims[(r0 + 8) * 33 + cb]     = acc[mt][nt][2];
            sims[(r0 + 8) * 33 + cb + 1] = acc[mt][nt][3];
        }
    }
    __syncthreads();

    // ---- epilogue: one thread per queue row ----------------------------------
    unsigned int* stage = (unsigned int*)(sm + SM_STAGE);
    int* s_wc   = (int*)(sm + SM_WC);
    int* s_lofs = (int*)(sm + SM_LOFS);
    int* s_base = (int*)(sm + SM_BASE);
    int* s_cnt  = (int*)(sm + SM_CNT);

    int clk = clu_k[k0 + t];
    int lbk = lab_k[k0 + t];
    float myS[32];
    #pragma unroll
    for (int b = 0; b < 32; b++) myS[b] = sims[t * 33 + b];

    #pragma unroll
    for (int b = 0; b < 32; b++) {
        int neg = (clk == s_clb[b]) != (lbk == s_lbb[b]);
        unsigned int mask = __ballot_sync(FULLMASK, neg);
        if (lane == 0) {
            int cn = __popc(mask);
            s_wc[(b * 2 + 1) * 4 + w] = cn;
            s_wc[(b * 2) * 4 + w] = 32 - cn;
        }
    }
    __syncthreads();
    if (t < 64) {
        int run = 0, st[4];
        #pragma unroll
        for (int ww = 0; ww < 4; ww++) { st[ww] = run; run += s_wc[t * 4 + ww]; }
        #pragma unroll
        for (int ww = 0; ww < 4; ww++) s_wc[t * 4 + ww] = st[ww];
        s_cnt[t] = run;
        int b = t >> 1, neg = t & 1;
        s_base[t] = run ? atomicAdd(neg ? &g_cntN[b] : &g_cntP[b], run) : 0;
    }
    __syncthreads();
    if (t == 0) {
        int run = 0;
        for (int s = 0; s < 64; s++) { s_lofs[s] = run; run += s_cnt[s]; }
    }
    __syncthreads();
    {
        unsigned int below = (1u << lane) - 1u;
        #pragma unroll
        for (int b = 0; b < 32; b++) {
            int neg = (clk == s_clb[b]) != (lbk == s_lbb[b]);
            unsigned int mask = __ballot_sync(FULLMASK, neg);
            int seg = b * 2 + neg;
            int rank = neg ? __popc(mask & below) : __popc(~mask & below);
            stage[s_lofs[seg] + s_wc[seg * 4 + w] + rank] = keyOf(myS[b]);
        }
    }
    __syncthreads();
    for (int s = w * 16; s < w * 16 + 16; s++) {
        int cnt = s_cnt[s];
        int b = s >> 1, neg = s & 1;
        unsigned int* dst = (neg ? g_bufN0 : g_bufP) + (size_t)b * KQ + s_base[s];
        const unsigned int* srcP = stage + s_lofs[s];
        for (int i = lane; i < cnt; i += 32) dst[i] = srcP[i];
    }
}

// ---------------- per-pass histogram, MLP-16 prefetch (+ fused minmax) ---------
__global__ void rs_hist(int shift, int srcSel, int doMinmax,
                        const int* __restrict__ topk) {
    int chunk = blockIdx.x, row = blockIdx.y;
    int t = threadIdx.x;
    if (doMinmax && chunk == 0 && row == 0 && t < 32) {
        int cp = g_cntP[t], cn = g_cntN[t];
        #pragma unroll
        for (int off = 16; off; off >>= 1) {
            cp = min(cp, __shfl_down_sync(FULLMASK, cp, off));
            cn = min(cn, __shfl_down_sync(FULLMASK, cn, off));
        }
        if (t == 0) { g_pmm[0] = min(cp, topk[0]); g_pmm[1] = cn; }
    }
    int n = g_cntN[row];
    int s0 = chunk * 4096;
    __shared__ int h[256];
    h[t] = 0;
    __syncthreads();
    if (s0 < n) {
        const unsigned int* in = (srcSel ? g_bufN1 : g_bufN0) + (size_t)row * KQ + s0;
        int lim = min(4096, n - s0);
        unsigned int keys[16];
        #pragma unroll
        for (int j = 0; j < 16; j++) {
            int i = j * 256 + t;
            keys[j] = (i < lim) ? in[i] : 0u;
        }
        #pragma unroll
        for (int j = 0; j < 16; j++) {
            int i = j * 256 + t;
            if (i < lim) atomicAdd(&h[(keys[j] >> shift) & 255], 1);
        }
    }
    __syncthreads();
    g_histA[row * 8192 + t * 32 + chunk] = h[t];
}

// ---------------- scan ---------------------------------------------------------
__global__ void rs_scan() {
    int row = blockIdx.x;
    unsigned int* a = g_histA + row * 8192;
    int t = threadIdx.x;
    int v[32]; int sum = 0;
    int base = t * 32;
    #pragma unroll
    for (int i = 0; i < 32; i++) { v[i] = (int)a[base + i]; sum += v[i]; }
    __shared__ int ps[256];
    ps[t] = sum;
    __syncthreads();
    for (int off = 1; off < 256; off <<= 1) {
        int x = (t >= off) ? ps[t - off] : 0;
        __syncthreads();
        ps[t] += x;
        __syncthreads();
    }
    int run = (t > 0) ? ps[t - 1] : 0;
    #pragma unroll
    for (int i = 0; i < 32; i++) { int tmp = v[i]; a[base + i] = (unsigned)run; run += tmp; }
}

// ---------------- top-10 of positives (4 blocks/row, 64 keys/thread) -----------
__device__ __forceinline__ void insert10(unsigned int (&best)[10], unsigned int k) {
    if (k < best[9]) {
        int j = 9;
        #pragma unroll
        for (int s = 0; s < 9; s++) {
            if (j > 0 && best[j - 1] > k) { best[j] = best[j - 1]; j--; }
        }
        best[j] = k;
    }
}

__global__ void pos_part() {
    int c = blockIdx.x, row = blockIdx.y;   // c in {0..3}
    int n = g_cntP[row];
    int per = (n + 3) >> 2;
    int s = c * per, e = min(s + per, n);
    const unsigned int* src = g_bufP + (size_t)row * KQ;
    int t = threadIdx.x;
    int w = t >> 5, lane = t & 31;
    unsigned int best[10];
    #pragma unroll
    for (int i = 0; i < 10; i++) best[i] = 0xFFFFFFFFu;
    for (int base = s; base < e; base += 2048) {
        unsigned int k[8];
        #pragma unroll
        for (int qn = 0; qn < 8; qn++) {
            int idx = base + qn * 256 + t;
            k[qn] = (idx < e) ? src[idx] : 0xFFFFFFFFu;
        }
        #pragma unroll
        for (int qn = 0; qn < 8; qn++) insert10(best, k[qn]);
    }
    __shared__ unsigned int sh[8 * 10];
    #pragma unroll
    for (int r = 0; r < 10; r++) {
        unsigned int cand = best[0];
        unsigned int wmin = cand;
        #pragma unroll
        for (int off = 16; off; off >>= 1)
            wmin = min(wmin, __shfl_xor_sync(FULLMASK, wmin, off));
        unsigned int bal = __ballot_sync(FULLMASK, cand == wmin);
        int leader = __ffs(bal) - 1;
        if (lane == leader) {
            #pragma unroll
            for (int i = 0; i < 9; i++) best[i] = best[i + 1];
            best[9] = 0xFFFFFFFFu;
        }
        if (lane == 0) sh[w * 10 + r] = wmin;
    }
    __syncthreads();
    if (w == 0) {
        int head = 0;
        for (int r = 0; r < 10; r++) {
            unsigned int cand = (lane < 8) ? sh[lane * 10 + head] : 0xFFFFFFFFu;
            unsigned int wmin = cand;
            #pragma unroll
            for (int off = 16; off; off >>= 1)
                wmin = min(wmin, __shfl_xor_sync(FULLMASK, wmin, off));
            unsigned int bal = __ballot_sync(FULLMASK, cand == wmin && lane < 8);
            int leader = __ffs(bal) - 1;
            if (lane == leader) head++;
            if (lane == 0) g_posPart[row * 40 + c * 10 + r] = wmin;
        }
    }
}

// ---------------- radix scatter (3 passes) -------------------------------------
__global__ __launch_bounds__(256)
void rs_scatter(int shift, int srcSel) {
    int chunk = blockIdx.x, row = blockIdx.y;
    int n = g_cntN[row];
    int s0 = chunk * 4096;
    if (s0 >= n) return;
    const unsigned int* in  = (srcSel ? g_bufN1 : g_bufN0) + (size_t)row * KQ;
    unsigned int*       out = (srcSel ? g_bufN0 : g_bufN1) + (size_t)row * KQ;
    const unsigned int* Hb  = g_histA + row * 8192;

    __shared__ unsigned int sKeys[4096];
    __shared__ int wh[8 * 256];
    __shared__ int gb[256];
    __shared__ int lofs[256];
    __shared__ int ps[256];

    int t = threadIdx.x;
    int w = t >> 5, lane = t & 31;
    int wbase = s0 + 512 * w;

    unsigned int myKeys[16];
    #pragma unroll
    for (int j = 0; j < 16; j++) {
        int idx = wbase + 32 * j + lane;
        myKeys[j] = (idx < n) ? in[idx] : 0xFFFFFFFFu;
    }

    #pragma unroll
    for (int qq = 0; qq < 8; qq++) wh[qq * 256 + t] = 0;
    __syncthreads();

    #pragma unroll
    for (int j = 0; j < 16; j++) {
        int idx = wbase + 32 * j + lane;
        if (idx < n) atomicAdd(&wh[w * 256 + ((myKeys[j] >> shift) & 255)], 1);
    }
    __syncthreads();

    int tot = 0; int wstart[8];
    #pragma unroll
    for (int ww = 0; ww < 8; ww++) { wstart[ww] = tot; tot += wh[ww * 256 + t]; }
    ps[t] = tot;
    gb[t] = (int)Hb[t * 32 + chunk];
    __syncthreads();
    for (int off = 1; off < 256; off <<= 1) {
        int x = (t >= off) ? ps[t - off] : 0;
        __syncthreads();
        ps[t] += x;
        __syncthreads();
    }
    int lo = ps[t] - tot;
    lofs[t] = lo;
    #pragma unroll
    for (int ww = 0; ww < 8; ww++) wh[ww * 256 + t] = lo + wstart[ww];
    __syncthreads();

    #pragma unroll
    for (int j = 0; j < 16; j++) {
        int idx = wbase + 32 * j + lane;
        bool val = idx < n;
        unsigned int key = myKeys[j];
        int d = (key >> shift) & 255;
        unsigned int vm = __ballot_sync(FULLMASK, val);
        unsigned int peers = FULLMASK;
        #pragma unroll
        for (int bb = 0; bb < 8; ++bb) {
            unsigned int vote = __ballot_sync(FULLMASK, (d >> bb) & 1);
            peers &= ((d >> bb) & 1) ? vote : ~vote;
        }
        peers &= vm;
        int rank = __popc(peers & ((1u << lane) - 1u));
        int leader = peers ? (__ffs(peers) - 1) : 0;
        int basePos = 0;
        if (val && rank == 0) basePos = atomicAdd(&wh[w * 256 + d], __popc(peers));
        basePos = __shfl_sync(FULLMASK, basePos, leader);
        if (val) sKeys[basePos + rank] = key;
    }
    __syncthreads();

    int lim = min(4096, n - s0);
    for (int pos = t; pos < lim; pos += 256) {
        unsigned int key = sKeys[pos];
        int d = (key >> shift) & 255;
        out[gb[d] + (pos - lofs[d])] = key;
    }
}

// ---------------- writer (final sorted negatives in g_bufN1) -------------------
__global__ void write_k(float* __restrict__ out) {
    int r = blockIdx.y;
    unsigned int pm = (unsigned int)g_pmm[0];
    unsigned int nm = (unsigned int)g_pmm[1];
    if ((unsigned)r >= 32u * pm) return;
    unsigned int width = nm + 1u;
    unsigned int b = (unsigned)r / pm;
    unsigned int p = (unsigned)r - b * pm;
    const float invT = 1.0f / 0.07f;
    size_t rowBase = (size_t)r * width;
    const unsigned int* negRow = g_bufN1 + (size_t)b * KQ;

    unsigned int qlen = (width + 3u) >> 2;
    unsigned int c = blockIdx.x * qlen + threadIdx.x;
    unsigned int cend = min((blockIdx.x + 1u) * qlen, width);
    if (c >= cend) return;
    if (c == 0u) {
        const unsigned int* parts = g_posPart + b * 40;
        unsigned int res = 0u;
        for (int j = 0; j < 40; j++) {
            unsigned int xj = parts[j];
            int rank = 0;
            #pragma unroll 8
            for (int i = 0; i < 40; i++) {
                unsigned int xi = parts[i];
                rank += (xi < xj) || (xi == xj && i < j);
            }
            if (rank == (int)p) res = xj;
        }
        out[rowBase] = valOf(res) * invT;
        c += 256u;
        if (c >= cend) return;
    }
    unsigned int num = p * nm + (c - 1u);
    unsigned int qi = num / pm;
    unsigned int rem = num - qi * pm;
    unsigned int d256 = 256u / pm;
    unsigned int r256 = 256u - d256 * pm;
    while (c < cend) {
        out[rowBase + c] = valOf(negRow[qi]) * invT;
        c += 256u;
        qi += d256;
        rem += r256;
        if (rem >= pm) { rem -= pm; qi += 1u; }
    }
}

// ---------------- launcher ----------------------------------------------------
extern "C" void kernel_launch(void* const* d_in, const int* in_sizes, int n_in,
                              void* d_out, int out_size) {
    const float* q     = (const float*)d_in[0];
    const float* fq    = (const float*)d_in[1];
    const int* lab_q   = (const int*)d_in[2];
    const int* clu_q   = (const int*)d_in[3];
    const int* lab_k   = (const int*)d_in[4];
    const int* clu_k   = (const int*)d_in[5];
    const int* topk    = (const int*)d_in[6];
    float* out = (float*)d_out;

    cudaFuncSetAttribute(mm_tc, cudaFuncAttributeMaxDynamicSharedMemorySize, SMEM_TC);

    prep_q<<<(B * H / 2 + 255) / 256, 256>>>(q);
    mm_tc<<<KQ / MROWS, TCTHREADS, SMEM_TC>>>(fq, lab_q, clu_q, lab_k, clu_k);
    pos_part<<<dim3(4, B), 256>>>();
    for (int pass = 0; pass < 3; ++pass) {
        int shift = 8 + pass * 8;
        rs_hist<<<dim3(32, B), 256>>>(shift, pass & 1, pass == 0, topk);
        rs_scan<<<B, 256>>>();
        rs_scatter<<<dim3(32, B), 256>>>(shift, pass & 1);
    }
    write_k<<<dim3(4, 320), 256>>>(out);
}